// round 4
// baseline (speedup 1.0000x reference)
#include <cuda_runtime.h>
#include <cuda_fp16.h>
#include <stdint.h>

#define Bq    64
#define Ec    8978
#define E2c   4489
#define N1    574592      // B*E
#define N2    287296      // B*E2
#define NE1   9193472     // N1*16
#define NE2   4596736     // N2*16
#define SLOPE 0.33f

// ---------------- scratch (device globals; no allocations) ----------------
__device__ float    dT1a[N1], dT2a[N1], dT3a[N1];
__device__ float    dX2[N2 * 32];
__device__ float    dT1v[N2 * 32], dT2v[N2 * 32];
__device__ float    dOutB[N2 * 32];
__device__ __half   dX2h[N2 * 32], dT1h[N2 * 32], dT2h[N2 * 32], dT3h[N2 * 32], dX3h[N2 * 32];
__device__ float    dXfPre[N2], dXf[N2];
__device__ double   dAcc[128];
__device__ float    dScale[33], dShift[33];
__device__ float    dH1[Bq * 256], dH2[Bq * 128];
__device__ uint16_t dLsrc1[NE1], dLsrc2[NE2];

// ---------------- preprocessing: local src ids + inits ----------------
// grid: [0,NBE) edges ; [NBE,NBE+64) H1 bias init ; +1 dAcc zero ; +1123 dXfPre zero
#define NBE 53868
__global__ void k_prep_edges(const int* __restrict__ src1, const int* __restrict__ src2,
                             const float* __restrict__ l1b) {
    int b = blockIdx.x;
    if (b < NBE) {
        long long i = (long long)b * 256 + threadIdx.x;
        if (i < NE1) {
            int g = (int)((i >> 4) / Ec);
            dLsrc1[i] = (uint16_t)(src1[i] - g * Ec);
        } else {
            long long j = i - NE1;   // j < NE2 always (NBE*256 == NE1+NE2)
            int g = (int)((j >> 4) / E2c);
            dLsrc2[j] = (uint16_t)(src2[j] - g * E2c);
        }
        return;
    }
    b -= NBE;
    if (b < 64) { dH1[b * 256 + threadIdx.x] = l1b[threadIdx.x]; return; }
    b -= 64;
    if (b < 1) { if (threadIdx.x < 128) dAcc[threadIdx.x] = 0.0; return; }
    b -= 1;
    int i = b * 256 + threadIdx.x;
    if (i < N2) dXfPre[i] = 0.f;
}

// ---------------- layer 0: scalar matvec, smem-resident graph vector --------
// out[i] = (alpha*v[i] + beta*p[i] - (L v)[i]) * gamma
// grid dim3(8 slices, 64 graphs), block 256
__global__ void k_mv_scalar_g(const float* __restrict__ v, const float* __restrict__ p,
                              float* __restrict__ out, const float* __restrict__ ew,
                              float alpha, float beta, float gamma) {
    __shared__ float vs[Ec];
    int g = blockIdx.y, s = blockIdx.x;
    int gbase = g * Ec;
    for (int i = threadIdx.x; i < Ec; i += 256) vs[i] = v[gbase + i];
    __syncthreads();
    int start = s * 1123;
    int cnt = Ec - start; if (cnt > 1123) cnt = 1123;
    int lane16 = threadIdx.x & 15;
    for (int idx = threadIdx.x >> 4; idx < cnt; idx += 16) {
        int node = start + idx;
        long long ge = ((long long)(gbase + node) << 4) + lane16;
        float sum = ew[ge] * vs[dLsrc1[ge]];
        sum += __shfl_down_sync(0xffffffffu, sum, 8, 16);
        sum += __shfl_down_sync(0xffffffffu, sum, 4, 16);
        sum += __shfl_down_sync(0xffffffffu, sum, 2, 16);
        sum += __shfl_down_sync(0xffffffffu, sum, 1, 16);
        if (lane16 == 0)
            out[gbase + node] = (alpha * vs[node] + beta * p[gbase + node] - sum) * gamma;
    }
}

// 4 means + 10 second moments of (x, T1, T2, T3) -> dAcc[0..14) ; float4 loads
__global__ void k_stats0(const float* __restrict__ x) {
    float loc[14];
#pragma unroll
    for (int i = 0; i < 14; i++) loc[i] = 0.f;
    const float4* X = (const float4*)x;
    const float4* A = (const float4*)dT1a;
    const float4* B = (const float4*)dT2a;
    const float4* C = (const float4*)dT3a;
    int stride = gridDim.x * blockDim.x;
    for (int i = blockIdx.x * blockDim.x + threadIdx.x; i < N1 / 4; i += stride) {
        float4 a = X[i], b = A[i], c = B[i], d = C[i];
        float t0[4] = {a.x, a.y, a.z, a.w};
        float t1[4] = {b.x, b.y, b.z, b.w};
        float t2[4] = {c.x, c.y, c.z, c.w};
        float t3[4] = {d.x, d.y, d.z, d.w};
#pragma unroll
        for (int u = 0; u < 4; u++) {
            loc[0] += t0[u]; loc[1] += t1[u]; loc[2] += t2[u]; loc[3] += t3[u];
            loc[4]  += t0[u] * t0[u]; loc[5]  += t0[u] * t1[u];
            loc[6]  += t0[u] * t2[u]; loc[7]  += t0[u] * t3[u];
            loc[8]  += t1[u] * t1[u]; loc[9]  += t1[u] * t2[u];
            loc[10] += t1[u] * t3[u]; loc[11] += t2[u] * t2[u];
            loc[12] += t2[u] * t3[u]; loc[13] += t3[u] * t3[u];
        }
    }
#pragma unroll
    for (int o = 16; o > 0; o >>= 1)
#pragma unroll
        for (int i = 0; i < 14; i++)
            loc[i] += __shfl_down_sync(0xffffffffu, loc[i], o);
    __shared__ double sh[8][14];
    int w = threadIdx.x >> 5, l = threadIdx.x & 31;
    if (l == 0)
        for (int i = 0; i < 14; i++) sh[w][i] = (double)loc[i];
    __syncthreads();
    if (threadIdx.x == 0) {
        for (int i = 0; i < 14; i++) {
            double s = 0;
            for (int w2 = 0; w2 < 8; w2++) s += sh[w2][i];
            atomicAdd(&dAcc[i], s);
        }
    }
}

// single block: layer-0 BN scale/shift (b0 dropped: BN is bias-invariant)
__global__ void k_prep0(const float* __restrict__ W0,
                        const float* __restrict__ g0, const float* __restrict__ be0) {
    int c = threadIdx.x;
    if (c >= 32) return;
    double m[4], w[4];
    for (int k = 0; k < 4; k++) { m[k] = dAcc[k] / (double)N1; w[k] = W0[k * 32 + c]; }
    double mean = 0.0;
    for (int k = 0; k < 4; k++) mean += m[k] * w[k];
    const int idx[4][4] = {{4,5,6,7},{5,8,9,10},{6,9,11,12},{7,10,12,13}};
    double var = 0;
    for (int k = 0; k < 4; k++)
        for (int l = 0; l < 4; l++)
            var += w[k] * w[l] * (dAcc[idx[k][l]] / (double)N1 - m[k] * m[l]);
    double sc = (double)g0[c] / sqrt(var + 1e-5);
    dScale[c] = (float)sc;
    dShift[c] = (float)((double)be0[c] - mean * sc);
}

// fused: project T->32ch, BN affine, LeakyReLU, Graclus pair-max pool
__global__ void k_pool(const float* __restrict__ x, const float* __restrict__ W0) {
    int t = blockIdx.x * blockDim.x + threadIdx.x;
    int p = t >> 5;
    if (p >= N2) return;
    int c = t & 31;
    float w0 = W0[c], w1 = W0[32 + c], w2 = W0[64 + c], w3 = W0[96 + c];
    float sc = dScale[c], sh = dShift[c];
    int n0 = 2 * p, n1 = 2 * p + 1;
    float o0 = x[n0] * w0 + dT1a[n0] * w1 + dT2a[n0] * w2 + dT3a[n0] * w3;
    float o1 = x[n1] * w0 + dT1a[n1] * w1 + dT2a[n1] * w2 + dT3a[n1] * w3;
    o0 = o0 * sc + sh; o0 = o0 > 0.f ? o0 : SLOPE * o0;
    o1 = o1 * sc + sh; o1 = o1 > 0.f ? o1 : SLOPE * o1;
    float r = fmaxf(o0, o1);
    dX2[p * 32 + c]  = r;
    dX2h[p * 32 + c] = __float2half(r);
}

// ---------------- layers 1/2: smem-resident 16-channel graph matvec --------
// grid dim3(4 slices, 2 ch-halves, 64 graphs), block 512, dyn smem 143648 B
__global__ void __launch_bounds__(512)
k_mv_vec_g(const float* __restrict__ vf, const __half* __restrict__ vh,
           const float* __restrict__ pf,
           float* __restrict__ out, __half* __restrict__ outh,
           const float* __restrict__ ew,
           float alpha, float beta, float gamma, int write_f32) {
    extern __shared__ unsigned int vs2[];          // [E2c*8] half2 pairs
    int g = blockIdx.z, h = blockIdx.y, s = blockIdx.x;
    int gbase = g * E2c;
    const unsigned int* vhu = (const unsigned int*)vh + (size_t)gbase * 16 + h * 8;
    for (int i = threadIdx.x; i < E2c * 8; i += 512)
        vs2[i] = vhu[(size_t)(i >> 3) * 16 + (i & 7)];
    __syncthreads();
    int start = s * 1123;
    int cnt = E2c - start; if (cnt > 1123) cnt = 1123;
    int warpid = threadIdx.x >> 5, lane = threadIdx.x & 31;
    int q = lane >> 3, j = lane & 7;
    for (int base = warpid * 4; base < cnt; base += 64) {
        int rel = base + q;
        bool valid = rel < cnt;
        int node = start + (valid ? rel : 0);
        long long eh = ((long long)(gbase + node)) * 8;   // edge-pair base (16 edges = 8 pairs)
        unsigned int sp = ((const unsigned int*)dLsrc2)[eh + j];
        float2 wp = ((const float2*)ew)[eh + j];
        float accx = 0.f, accy = 0.f;
#pragma unroll
        for (int k = 0; k < 8; k++) {
            int sl_ = q * 8 + k;
            unsigned int sk = __shfl_sync(0xffffffffu, sp, sl_);
            float w0 = __shfl_sync(0xffffffffu, wp.x, sl_);
            float w1 = __shfl_sync(0xffffffffu, wp.y, sl_);
            unsigned int ua = vs2[(sk & 0xffffu) * 8 + j];
            unsigned int ub = vs2[(sk >> 16) * 8 + j];
            float2 fa = __half22float2(*reinterpret_cast<__half2*>(&ua));
            float2 fb = __half22float2(*reinterpret_cast<__half2*>(&ub));
            accx += w0 * fa.x + w1 * fb.x;
            accy += w0 * fa.y + w1 * fb.y;
        }
        if (valid) {
            size_t o = (size_t)(gbase + node) * 32 + h * 16 + 2 * j;
            float2 vv = *(const float2*)(vf + o);
            float2 pp = *(const float2*)(pf + o);
            float rx = (alpha * vv.x + beta * pp.x - accx) * gamma;
            float ry = (alpha * vv.y + beta * pp.y - accy) * gamma;
            if (write_f32) *(float2*)(out + o) = make_float2(rx, ry);
            *(__half2*)(outh + o) = __floats2half2_rn(rx, ry);
        }
    }
}

// layer-2 final pass: gather T2, form T3, fused 1-channel projection (partial
// over this block's 16 channels) -> atomicAdd into dXfPre
__global__ void __launch_bounds__(512)
k_mv_out2_g(const float* __restrict__ vf, const __half* __restrict__ vh,
            const float* __restrict__ pf, const float* __restrict__ x3f,
            const float* __restrict__ ew, const float* __restrict__ W2) {
    extern __shared__ unsigned int vs2[];
    int g = blockIdx.z, h = blockIdx.y, s = blockIdx.x;
    int gbase = g * E2c;
    const unsigned int* vhu = (const unsigned int*)vh + (size_t)gbase * 16 + h * 8;
    for (int i = threadIdx.x; i < E2c * 8; i += 512)
        vs2[i] = vhu[(size_t)(i >> 3) * 16 + (i & 7)];
    __syncthreads();
    int start = s * 1123;
    int cnt = E2c - start; if (cnt > 1123) cnt = 1123;
    int warpid = threadIdx.x >> 5, lane = threadIdx.x & 31;
    int q = lane >> 3, j = lane & 7;
    int jc = h * 16 + 2 * j;
    float2 w20 = *(const float2*)(W2 + jc);
    float2 w21 = *(const float2*)(W2 + 32 + jc);
    float2 w22 = *(const float2*)(W2 + 64 + jc);
    float2 w23 = *(const float2*)(W2 + 96 + jc);
    for (int base = warpid * 4; base < cnt; base += 64) {
        int rel = base + q;
        bool valid = rel < cnt;
        int node = start + (valid ? rel : 0);
        long long eh = ((long long)(gbase + node)) * 8;
        unsigned int sp = ((const unsigned int*)dLsrc2)[eh + j];
        float2 wp = ((const float2*)ew)[eh + j];
        float accx = 0.f, accy = 0.f;
#pragma unroll
        for (int k = 0; k < 8; k++) {
            int sl_ = q * 8 + k;
            unsigned int sk = __shfl_sync(0xffffffffu, sp, sl_);
            float w0 = __shfl_sync(0xffffffffu, wp.x, sl_);
            float w1 = __shfl_sync(0xffffffffu, wp.y, sl_);
            unsigned int ua = vs2[(sk & 0xffffu) * 8 + j];
            unsigned int ub = vs2[(sk >> 16) * 8 + j];
            float2 fa = __half22float2(*reinterpret_cast<__half2*>(&ua));
            float2 fb = __half22float2(*reinterpret_cast<__half2*>(&ub));
            accx += w0 * fa.x + w1 * fb.x;
            accy += w0 * fa.y + w1 * fb.y;
        }
        float pn = 0.f;
        int gnode = gbase + node;
        if (valid) {
            size_t o = (size_t)gnode * 32 + h * 16 + 2 * j;
            float2 vv = *(const float2*)(vf + o);     // T2
            float2 pp = *(const float2*)(pf + o);     // T1
            float2 xx = *(const float2*)(x3f + o);    // layer-2 input
            float t3x = (5.f * vv.x - 2.f * pp.x - accx) * (1.f / 3.f);
            float t3y = (5.f * vv.y - 2.f * pp.y - accy) * (1.f / 3.f);
            pn = xx.x * w20.x + xx.y * w20.y + pp.x * w21.x + pp.y * w21.y +
                 vv.x * w22.x + vv.y * w22.y + t3x * w23.x + t3y * w23.y;
        }
        pn += __shfl_down_sync(0xffffffffu, pn, 4, 8);
        pn += __shfl_down_sync(0xffffffffu, pn, 2, 8);
        pn += __shfl_down_sync(0xffffffffu, pn, 1, 8);
        if (j == 0 && valid) atomicAdd(&dXfPre[gnode], pn);
    }
}

// out = [A0|A1|A2|A3](fp16) @ W(128x32) + bias
__global__ void k_outgemm(const __half* __restrict__ A0, const __half* __restrict__ A1,
                          const __half* __restrict__ A2, const __half* __restrict__ A3,
                          const float* __restrict__ W,  const float* __restrict__ bias,
                          float* __restrict__ out) {
    extern __shared__ __align__(16) float smem[];
    float* Ws = smem;            // 4096 floats
    float* As = smem + 4096;     // 128*129 floats
    int t = threadIdx.x;
    int nb = blockIdx.x * 128;
    for (int i = t; i < 4096; i += 256) Ws[i] = W[i];
    for (int i = t; i < 4096; i += 256) {
        int n = i >> 5, jj = i & 31, gg = nb + n;
        float v0 = 0, v1 = 0, v2 = 0, v3 = 0;
        if (gg < N2) {
            size_t o = (size_t)gg * 32 + jj;
            v0 = __half2float(A0[o]); v1 = __half2float(A1[o]);
            v2 = __half2float(A2[o]); v3 = __half2float(A3[o]);
        }
        As[n * 129 + jj] = v0; As[n * 129 + 32 + jj] = v1;
        As[n * 129 + 64 + jj] = v2; As[n * 129 + 96 + jj] = v3;
    }
    __syncthreads();
    int cg = (t & 7) * 4, n0 = (t >> 3) * 4;
    float acc[4][4];
#pragma unroll
    for (int i = 0; i < 4; i++)
#pragma unroll
        for (int c = 0; c < 4; c++) acc[i][c] = 0.f;
#pragma unroll 4
    for (int jj = 0; jj < 128; jj++) {
        float4 w = *(const float4*)&Ws[jj * 32 + cg];
        float a0 = As[n0 * 129 + jj], a1 = As[(n0 + 1) * 129 + jj];
        float a2 = As[(n0 + 2) * 129 + jj], a3 = As[(n0 + 3) * 129 + jj];
        acc[0][0] += a0 * w.x; acc[0][1] += a0 * w.y; acc[0][2] += a0 * w.z; acc[0][3] += a0 * w.w;
        acc[1][0] += a1 * w.x; acc[1][1] += a1 * w.y; acc[1][2] += a1 * w.z; acc[1][3] += a1 * w.w;
        acc[2][0] += a2 * w.x; acc[2][1] += a2 * w.y; acc[2][2] += a2 * w.z; acc[2][3] += a2 * w.w;
        acc[3][0] += a3 * w.x; acc[3][1] += a3 * w.y; acc[3][2] += a3 * w.z; acc[3][3] += a3 * w.w;
    }
#pragma unroll
    for (int i = 0; i < 4; i++) {
        int gg = nb + n0 + i;
        if (gg < N2)
#pragma unroll
            for (int c = 0; c < 4; c++)
                out[(size_t)gg * 32 + cg + c] = acc[i][c] + bias[cg + c];
    }
}

// per-channel sum/sumsq over [N2,32] -> dAcc[16..80) ; float4
__global__ void k_stats32(const float* __restrict__ a) {
    __shared__ double ss[32], sq[32];
    int t = threadIdx.x;
    if (t < 32) { ss[t] = 0; sq[t] = 0; }
    __syncthreads();
    const float4* a4 = (const float4*)a;
    int stride = gridDim.x * blockDim.x;          // multiple of 8
    int i0 = blockIdx.x * blockDim.x + t;
    int cg = (i0 & 7) * 4;
    float s[4] = {0, 0, 0, 0}, q[4] = {0, 0, 0, 0};
    for (int i = i0; i < N2 * 8; i += stride) {
        float4 v = a4[i];
        s[0] += v.x; q[0] += v.x * v.x;
        s[1] += v.y; q[1] += v.y * v.y;
        s[2] += v.z; q[2] += v.z * v.z;
        s[3] += v.w; q[3] += v.w * v.w;
    }
#pragma unroll
    for (int u = 0; u < 4; u++) {
        atomicAdd(&ss[cg + u], (double)s[u]);
        atomicAdd(&sq[cg + u], (double)q[u]);
    }
    __syncthreads();
    if (t < 32) { atomicAdd(&dAcc[16 + t], ss[t]); atomicAdd(&dAcc[48 + t], sq[t]); }
}

__global__ void k_prep32(const float* __restrict__ g, const float* __restrict__ be) {
    int c = threadIdx.x;
    if (c >= 32) return;
    double mean = dAcc[16 + c] / (double)N2;
    double var  = dAcc[48 + c] / (double)N2 - mean * mean;
    double sc = (double)g[c] / sqrt(var + 1e-5);
    dScale[c] = (float)sc;
    dShift[c] = (float)((double)be[c] - mean * sc);
}

__global__ void k_apply32(float* __restrict__ a, __half* __restrict__ ah) {
    int i = blockIdx.x * blockDim.x + threadIdx.x;
    int c = i & 31;
    float v = a[i] * dScale[c] + dShift[c];
    v = v > 0.f ? v : SLOPE * v;
    a[i]  = v;
    ah[i] = __float2half(v);
}

// scalar sum/sumsq over dXfPre -> dAcc[96,97]
__global__ void k_statsF() {
    const float4* a4 = (const float4*)dXfPre;
    int stride = gridDim.x * blockDim.x;
    float s = 0.f, q = 0.f;
    for (int i = blockIdx.x * blockDim.x + threadIdx.x; i < N2 / 4; i += stride) {
        float4 v = a4[i];
        s += v.x + v.y + v.z + v.w;
        q += v.x * v.x + v.y * v.y + v.z * v.z + v.w * v.w;
    }
#pragma unroll
    for (int o = 16; o > 0; o >>= 1) {
        s += __shfl_down_sync(0xffffffffu, s, o);
        q += __shfl_down_sync(0xffffffffu, q, o);
    }
    __shared__ float shs[8], shq[8];
    int w = threadIdx.x >> 5;
    if ((threadIdx.x & 31) == 0) { shs[w] = s; shq[w] = q; }
    __syncthreads();
    if (threadIdx.x == 0) {
        float ts = 0, tq = 0;
        for (int i = 0; i < 8; i++) { ts += shs[i]; tq += shq[i]; }
        atomicAdd(&dAcc[96], (double)ts);
        atomicAdd(&dAcc[97], (double)tq);
    }
}

// layer-2 scalar BN prep (b2 cancels under BN)
__global__ void k_prep1(const float* __restrict__ g, const float* __restrict__ be) {
    double mean = dAcc[96] / (double)N2;
    double var  = dAcc[97] / (double)N2 - mean * mean;
    double sc = (double)g[0] / sqrt(var + 1e-5);
    dScale[32] = (float)sc;
    dShift[32] = (float)((double)be[0] - mean * sc);
}

__global__ void k_apply1() {
    int i = blockIdx.x * blockDim.x + threadIdx.x;
    if (i >= N2) return;
    float v = dXfPre[i] * dScale[32] + dShift[32];
    dXf[i] = v > 0.f ? v : SLOPE * v;
}

// ---------------- MLP head ----------------
__global__ void k_lin1(const float* __restrict__ W) {
    __shared__ float sm[16 * 128];
    int c = threadIdx.x;
    int jbase = blockIdx.x * 128;
    int rbase = blockIdx.y * 16;
    for (int i = c; i < 16 * 128; i += 256) {
        int r = i >> 7, jj = i & 127, gj = jbase + jj;
        sm[i] = (gj < E2c) ? dXf[(rbase + r) * E2c + gj] : 0.f;
    }
    __syncthreads();
    int jlim = E2c - jbase; if (jlim > 128) jlim = 128;
    float acc[16];
#pragma unroll
    for (int r = 0; r < 16; r++) acc[r] = 0.f;
    for (int jj = 0; jj < jlim; jj++) {
        float w = __ldg(&W[(jbase + jj) * 256 + c]);
#pragma unroll
        for (int r = 0; r < 16; r++) acc[r] += sm[r * 128 + jj] * w;
    }
#pragma unroll
    for (int r = 0; r < 16; r++)
        atomicAdd(&dH1[(rbase + r) * 256 + c], acc[r]);
}

__global__ void k_bnrelu(float* __restrict__ H, const float* __restrict__ g,
                         const float* __restrict__ be, int C) {
    int c = threadIdx.x;
    if (c >= C) return;
    float s = 0, q = 0;
    for (int r = 0; r < Bq; r++) { float v = H[r * C + c]; s += v; q += v * v; }
    float mean = s / (float)Bq, var = q / (float)Bq - mean * mean;
    float sc = g[c] * rsqrtf(var + 1e-5f);
    float sh = be[c] - mean * sc;
    for (int r = 0; r < Bq; r++) {
        float v = H[r * C + c] * sc + sh;
        H[r * C + c] = fmaxf(v, 0.f);
    }
}

__global__ void k_lin2(const float* __restrict__ H1, const float* __restrict__ W,
                       const float* __restrict__ bias, float* __restrict__ H2) {
    __shared__ float row[256];
    int b = blockIdx.x, t = threadIdx.x;
    row[t] = H1[b * 256 + t];
    __syncthreads();
    if (t < 128) {
        float acc = bias[t];
        for (int jj = 0; jj < 256; jj++)
            acc += row[jj] * W[jj * 128 + t];
        H2[b * 128 + t] = acc;
    }
}

__global__ void k_lin3(const float* __restrict__ H2, const float* __restrict__ W,
                       const float* __restrict__ bias, float* __restrict__ out) {
    int b = blockIdx.x, t = threadIdx.x;
    float p = H2[b * 128 + t] * W[t];
#pragma unroll
    for (int o = 16; o > 0; o >>= 1)
        p += __shfl_down_sync(0xffffffffu, p, o);
    __shared__ float sh[4];
    if ((t & 31) == 0) sh[t >> 5] = p;
    __syncthreads();
    if (t == 0) out[b] = sh[0] + sh[1] + sh[2] + sh[3] + bias[0];
}

// ---------------- launch ----------------
extern "C" void kernel_launch(void* const* d_in, const int* in_sizes, int n_in,
                              void* d_out, int out_size) {
    const float* x_s  = (const float*)d_in[0];
    const int*   ei1  = (const int*)d_in[1];
    const float* ew1  = (const float*)d_in[2];
    const int*   ei2  = (const int*)d_in[3];
    const float* ew2  = (const float*)d_in[4];
    const float* W0   = (const float*)d_in[5];
    const float* g0   = (const float*)d_in[7];
    const float* be0  = (const float*)d_in[8];
    const float* W1   = (const float*)d_in[9];
    const float* b1   = (const float*)d_in[10];
    const float* g1   = (const float*)d_in[11];
    const float* be1  = (const float*)d_in[12];
    const float* W2   = (const float*)d_in[13];
    const float* g2   = (const float*)d_in[15];
    const float* be2  = (const float*)d_in[16];
    const float* l1W  = (const float*)d_in[17];
    const float* l1b  = (const float*)d_in[18];
    const float* bn1g = (const float*)d_in[19];
    const float* bn1b = (const float*)d_in[20];
    const float* l2W  = (const float*)d_in[21];
    const float* l2b  = (const float*)d_in[22];
    const float* bn2g = (const float*)d_in[23];
    const float* bn2b = (const float*)d_in[24];
    const float* l3W  = (const float*)d_in[25];
    const float* l3b  = (const float*)d_in[26];

    float *pT1a, *pT2a, *pT3a, *pX2, *pT1, *pT2, *pOut, *pH1, *pH2;
    __half *pX2h, *pT1h, *pT2h, *pT3h, *pX3h;
    cudaGetSymbolAddress((void**)&pT1a, dT1a);
    cudaGetSymbolAddress((void**)&pT2a, dT2a);
    cudaGetSymbolAddress((void**)&pT3a, dT3a);
    cudaGetSymbolAddress((void**)&pX2, dX2);
    cudaGetSymbolAddress((void**)&pT1, dT1v);
    cudaGetSymbolAddress((void**)&pT2, dT2v);
    cudaGetSymbolAddress((void**)&pOut, dOutB);
    cudaGetSymbolAddress((void**)&pH1, dH1);
    cudaGetSymbolAddress((void**)&pH2, dH2);
    cudaGetSymbolAddress((void**)&pX2h, dX2h);
    cudaGetSymbolAddress((void**)&pT1h, dT1h);
    cudaGetSymbolAddress((void**)&pT2h, dT2h);
    cudaGetSymbolAddress((void**)&pT3h, dT3h);
    cudaGetSymbolAddress((void**)&pX3h, dX3h);

    static const int GEMM_SMEM = (4096 + 128 * 129) * 4;
    static const int VEC_SMEM  = E2c * 8 * 4;     // 143648 B
    cudaFuncSetAttribute(k_outgemm, cudaFuncAttributeMaxDynamicSharedMemorySize, GEMM_SMEM);
    cudaFuncSetAttribute(k_mv_vec_g, cudaFuncAttributeMaxDynamicSharedMemorySize, VEC_SMEM);
    cudaFuncSetAttribute(k_mv_out2_g, cudaFuncAttributeMaxDynamicSharedMemorySize, VEC_SMEM);

    const dim3 GRID_S(8, 64);
    const dim3 GRID_V(4, 2, 64);
    const int NBV = (N2 * 32) / 256;

    // ---- preprocessing + init ----
    k_prep_edges<<<NBE + 64 + 1 + 1123, 256>>>(ei1, ei2, l1b);

    // ---- layer 0 (scalar Laguerre conv, smem graph vector) ----
    k_mv_scalar_g<<<GRID_S, 256>>>(x_s, x_s, pT1a, ew1, 1.f, 0.f, 1.f);
    k_mv_scalar_g<<<GRID_S, 256>>>(pT1a, x_s, pT2a, ew1, 3.f, -1.f, 0.5f);
    k_mv_scalar_g<<<GRID_S, 256>>>(pT2a, pT1a, pT3a, ew1, 5.f, -2.f, 1.f / 3.f);
    k_stats0<<<562, 256>>>(x_s);
    k_prep0<<<1, 32>>>(W0, g0, be0);
    k_pool<<<NBV, 256>>>(x_s, W0);

    // ---- layer 1 (32ch Laguerre conv) ----
    k_mv_vec_g<<<GRID_V, 512, VEC_SMEM>>>(pX2, pX2h, pX2, pT1, pT1h, ew2, 1.f, 0.f, 1.f, 1);
    k_mv_vec_g<<<GRID_V, 512, VEC_SMEM>>>(pT1, pT1h, pX2, pT2, pT2h, ew2, 3.f, -1.f, 0.5f, 1);
    k_mv_vec_g<<<GRID_V, 512, VEC_SMEM>>>(pT2, pT2h, pT1, pT2, pT3h, ew2, 5.f, -2.f, 1.f / 3.f, 0);
    k_outgemm<<<(N2 + 127) / 128, 256, GEMM_SMEM>>>(pX2h, pT1h, pT2h, pT3h, W1, b1, pOut);
    k_stats32<<<1122, 256>>>(pOut);
    k_prep32<<<1, 32>>>(g1, be1);
    k_apply32<<<NBV, 256>>>(pOut, pX3h);

    // ---- layer 2 (32ch -> 1ch, final pass fused) ----
    k_mv_vec_g<<<GRID_V, 512, VEC_SMEM>>>(pOut, pX3h, pOut, pT1, pT1h, ew2, 1.f, 0.f, 1.f, 1);
    k_mv_vec_g<<<GRID_V, 512, VEC_SMEM>>>(pT1, pT1h, pOut, pT2, pT2h, ew2, 3.f, -1.f, 0.5f, 1);
    k_mv_out2_g<<<GRID_V, 512, VEC_SMEM>>>(pT2, pT2h, pT1, pOut, ew2, W2);
    k_statsF<<<281, 256>>>();
    k_prep1<<<1, 1>>>(g2, be2);
    k_apply1<<<(N2 + 255) / 256, 256>>>();

    // ---- MLP head ----
    k_lin1<<<dim3(36, 4), 256>>>(l1W);
    k_bnrelu<<<1, 256>>>(pH1, bn1g, bn1b, 256);
    k_lin2<<<Bq, 256>>>(pH1, l2W, l2b, pH2);
    k_bnrelu<<<1, 128>>>(pH2, bn2g, bn2b, 128);
    k_lin3<<<Bq, 128>>>(pH2, l3W, l3b, (float*)d_out);
}

// round 5
// speedup vs baseline: 1.8730x; 1.8730x over previous
#include <cuda_runtime.h>
#include <cuda_fp16.h>
#include <mma.h>
using namespace nvcuda;

#define Bq   64
#define E2c  4489
#define N1   574592      // B*E   = 64*8978
#define N2   287296      // B*E2  = 64*4489
#define NE1  9193472     // N1*16
#define NE2  4596736     // N2*16
#define SLOPE 0.33f

// ---------------- scratch (device globals; no allocations) ----------------
__device__ float  dT1a[N1], dT2a[N1], dT3a[N1];
__device__ float  dX2[N2 * 32];
__device__ float  dT1v[N2 * 32], dT2v[N2 * 32];
__device__ float  dOutB[N2 * 32];
__device__ __half dX2h[N2 * 32], dT1h[N2 * 32], dT2h[N2 * 32], dT3h[N2 * 32], dX3h[N2 * 32];
__device__ float  dXfPre[N2], dXf[N2];
__device__ double dAcc[128];
__device__ float  dScale[33], dShift[33];     // [32] = layer-2 scalar BN
__device__ float  dH1[Bq * 256], dH2[Bq * 128];

// ---------------- layer 0: scalar matvec + Laguerre combine ----------------
// out[i] = (alpha*v[i] + beta*p[i] - (L v)[i]) * gamma ; 16 threads per node
// first launch carries 65 tail blocks: 64 init H1 with bias, 1 zeros dAcc
__global__ void k_mv_scalar(const float* __restrict__ v, const float* __restrict__ p,
                            float* __restrict__ out, const int* __restrict__ src,
                            const float* __restrict__ ew, int n,
                            float alpha, float beta, float gamma,
                            const float* __restrict__ l1b) {
    int nb_main = n >> 4;
    if ((int)blockIdx.x >= nb_main) {         // init tail (only present on launch 1)
        int ib = blockIdx.x - nb_main;
        if (ib < 64) dH1[ib * 256 + threadIdx.x] = l1b[threadIdx.x];
        else if (threadIdx.x < 128) dAcc[threadIdx.x] = 0.0;
        return;
    }
    int t = blockIdx.x * blockDim.x + threadIdx.x;
    int node = t >> 4;
    int e = (node << 4) | (t & 15);
    float s = ew[e] * __ldg(&v[src[e]]);
    s += __shfl_down_sync(0xffffffffu, s, 8, 16);
    s += __shfl_down_sync(0xffffffffu, s, 4, 16);
    s += __shfl_down_sync(0xffffffffu, s, 2, 16);
    s += __shfl_down_sync(0xffffffffu, s, 1, 16);
    if ((t & 15) == 0)
        out[node] = (alpha * v[node] + beta * p[node] - s) * gamma;
}

// 4 means + 10 second moments of (x, T1, T2, T3) -> dAcc[0..14) ; float4 loads
__global__ void k_stats0(const float* __restrict__ x) {
    float loc[14];
#pragma unroll
    for (int i = 0; i < 14; i++) loc[i] = 0.f;
    const float4* X = (const float4*)x;
    const float4* A = (const float4*)dT1a;
    const float4* B = (const float4*)dT2a;
    const float4* C = (const float4*)dT3a;
    int stride = gridDim.x * blockDim.x;
    for (int i = blockIdx.x * blockDim.x + threadIdx.x; i < N1 / 4; i += stride) {
        float4 a = X[i], b = A[i], c = B[i], d = C[i];
        float t0[4] = {a.x, a.y, a.z, a.w};
        float t1[4] = {b.x, b.y, b.z, b.w};
        float t2[4] = {c.x, c.y, c.z, c.w};
        float t3[4] = {d.x, d.y, d.z, d.w};
#pragma unroll
        for (int u = 0; u < 4; u++) {
            loc[0] += t0[u]; loc[1] += t1[u]; loc[2] += t2[u]; loc[3] += t3[u];
            loc[4]  += t0[u] * t0[u]; loc[5]  += t0[u] * t1[u];
            loc[6]  += t0[u] * t2[u]; loc[7]  += t0[u] * t3[u];
            loc[8]  += t1[u] * t1[u]; loc[9]  += t1[u] * t2[u];
            loc[10] += t1[u] * t3[u]; loc[11] += t2[u] * t2[u];
            loc[12] += t2[u] * t3[u]; loc[13] += t3[u] * t3[u];
        }
    }
#pragma unroll
    for (int o = 16; o > 0; o >>= 1)
#pragma unroll
        for (int i = 0; i < 14; i++)
            loc[i] += __shfl_down_sync(0xffffffffu, loc[i], o);
    __shared__ double sh[8][14];
    int w = threadIdx.x >> 5, l = threadIdx.x & 31;
    if (l == 0)
        for (int i = 0; i < 14; i++) sh[w][i] = (double)loc[i];
    __syncthreads();
    if (threadIdx.x == 0) {
        for (int i = 0; i < 14; i++) {
            double s = 0;
            for (int w2 = 0; w2 < 8; w2++) s += sh[w2][i];
            atomicAdd(&dAcc[i], s);
        }
    }
}

// single block: layer-0 BN scale/shift from moments (exact; b0 is BN-invariant)
__global__ void k_prep0(const float* __restrict__ W0,
                        const float* __restrict__ g0, const float* __restrict__ be0) {
    int c = threadIdx.x;
    if (c >= 32) return;
    double m[4], w[4];
    for (int k = 0; k < 4; k++) { m[k] = dAcc[k] / (double)N1; w[k] = W0[k * 32 + c]; }
    double mean = 0.0;
    for (int k = 0; k < 4; k++) mean += m[k] * w[k];
    const int idx[4][4] = {{4,5,6,7},{5,8,9,10},{6,9,11,12},{7,10,12,13}};
    double var = 0;
    for (int k = 0; k < 4; k++)
        for (int l = 0; l < 4; l++)
            var += w[k] * w[l] * (dAcc[idx[k][l]] / (double)N1 - m[k] * m[l]);
    double sc = (double)g0[c] / sqrt(var + 1e-5);
    dScale[c] = (float)sc;
    dShift[c] = (float)((double)be0[c] - mean * sc);
}

// fused: project T->32ch, BN affine (precomputed), LeakyReLU, Graclus pair-max pool
__global__ void k_pool(const float* __restrict__ x, const float* __restrict__ W0) {
    int t = blockIdx.x * blockDim.x + threadIdx.x;
    int p = t >> 5;
    if (p >= N2) return;
    int c = t & 31;
    float w0 = W0[c], w1 = W0[32 + c], w2 = W0[64 + c], w3 = W0[96 + c];
    float sc = dScale[c], sh = dShift[c];
    int n0 = 2 * p, n1 = 2 * p + 1;
    float o0 = x[n0] * w0 + dT1a[n0] * w1 + dT2a[n0] * w2 + dT3a[n0] * w3;
    float o1 = x[n1] * w0 + dT1a[n1] * w1 + dT2a[n1] * w2 + dT3a[n1] * w3;
    o0 = o0 * sc + sh; o0 = o0 > 0.f ? o0 : SLOPE * o0;
    o1 = o1 * sc + sh; o1 = o1 > 0.f ? o1 : SLOPE * o1;
    float r = fmaxf(o0, o1);
    dX2[p * 32 + c]  = r;
    dX2h[p * 32 + c] = __float2half(r);
}

// ---------------- layers 1/2: 32-dim matvec + Laguerre combine -------------
// warp per node, lane = feature; gathers from fp16 copy, fp32 points/accumulate
__global__ void k_mv_vec(const float* __restrict__ v, const __half* __restrict__ vh,
                         const float* __restrict__ p,
                         float* __restrict__ out, __half* __restrict__ outh,
                         const int* __restrict__ src, const float* __restrict__ ew,
                         float alpha, float beta, float gamma, int write_f32) {
    int t = blockIdx.x * blockDim.x + threadIdx.x;
    int node = t >> 5;
    int lane = t & 31;
    int base = node * 16;
    int   sl = src[base + (lane & 15)];
    float wl = ew[base + (lane & 15)];
    float acc = 0.f;
#pragma unroll
    for (int e = 0; e < 16; e++) {
        int   s  = __shfl_sync(0xffffffffu, sl, e);
        float wt = __shfl_sync(0xffffffffu, wl, e);
        acc += wt * __half2float(__ldg(&vh[s * 32 + lane]));
    }
    int o = node * 32 + lane;
    float r = (alpha * __ldg(&v[o]) + beta * __ldg(&p[o]) - acc) * gamma;
    if (write_f32) out[o] = r;
    outh[o] = __float2half(r);
}

// out = [A0|A1|A2|A3](fp16) @ W(128x32), tensor cores (bias dropped: BN-invariant)
__global__ void __launch_bounds__(256)
k_outgemm_mma(const __half* __restrict__ A0, const __half* __restrict__ A1,
              const __half* __restrict__ A2, const __half* __restrict__ A3,
              const float* __restrict__ W, float* __restrict__ out) {
    __shared__ __half As[128][136];
    __shared__ __half Ws[128][40];
    int t = threadIdx.x;
    int nb = blockIdx.x * 128;
    for (int i = t; i < 4096; i += 256) {
        int k = i >> 5, c = i & 31;
        Ws[k][c] = __float2half(W[i]);        // W[(stage*32+j)*32+c]
    }
    for (int i = t; i < 4096; i += 256) {
        int n = i >> 5, c = i & 31;
        int g = nb + n;
        __half v0 = __float2half(0.f), v1 = v0, v2 = v0, v3 = v0;
        if (g < N2) {
            size_t o = (size_t)g * 32 + c;
            v0 = A0[o]; v1 = A1[o]; v2 = A2[o]; v3 = A3[o];
        }
        As[n][c] = v0; As[n][32 + c] = v1; As[n][64 + c] = v2; As[n][96 + c] = v3;
    }
    __syncthreads();
    int w = t >> 5;    // 8 warps, each owns a 16-row strip
    wmma::fragment<wmma::accumulator, 16, 16, 16, float> c0, c1;
    wmma::fill_fragment(c0, 0.f);
    wmma::fill_fragment(c1, 0.f);
#pragma unroll
    for (int k0 = 0; k0 < 8; k0++) {
        wmma::fragment<wmma::matrix_a, 16, 16, 16, __half, wmma::row_major> a;
        wmma::load_matrix_sync(a, &As[w * 16][k0 * 16], 136);
        wmma::fragment<wmma::matrix_b, 16, 16, 16, __half, wmma::row_major> b;
        wmma::load_matrix_sync(b, &Ws[k0 * 16][0], 40);
        wmma::mma_sync(c0, a, b, c0);
        wmma::load_matrix_sync(b, &Ws[k0 * 16][16], 40);
        wmma::mma_sync(c1, a, b, c1);
    }
    int row = nb + w * 16;
    if (row < N2) {   // N2 % 16 == 0, so tile fully valid
        wmma::store_matrix_sync(out + (size_t)row * 32, c0, 32, wmma::mem_row_major);
        wmma::store_matrix_sync(out + (size_t)row * 32 + 16, c1, 32, wmma::mem_row_major);
    }
}

// per-channel sum/sumsq over [N2,32] -> dAcc[16..80) ; float4
__global__ void k_stats32(const float* __restrict__ a) {
    __shared__ double ss[32], sq[32];
    int t = threadIdx.x;
    if (t < 32) { ss[t] = 0; sq[t] = 0; }
    __syncthreads();
    const float4* a4 = (const float4*)a;
    int stride = gridDim.x * blockDim.x;          // multiple of 8 (grid 1122*256)
    int i0 = blockIdx.x * blockDim.x + t;
    int cg = (i0 & 7) * 4;
    float s[4] = {0, 0, 0, 0}, q[4] = {0, 0, 0, 0};
    for (int i = i0; i < N2 * 8; i += stride) {
        float4 v = a4[i];
        s[0] += v.x; q[0] += v.x * v.x;
        s[1] += v.y; q[1] += v.y * v.y;
        s[2] += v.z; q[2] += v.z * v.z;
        s[3] += v.w; q[3] += v.w * v.w;
    }
#pragma unroll
    for (int u = 0; u < 4; u++) {
        atomicAdd(&ss[cg + u], (double)s[u]);
        atomicAdd(&sq[cg + u], (double)q[u]);
    }
    __syncthreads();
    if (t < 32) { atomicAdd(&dAcc[16 + t], ss[t]); atomicAdd(&dAcc[48 + t], sq[t]); }
}

// single block: layer-1 BN scale/shift
__global__ void k_prep32(const float* __restrict__ g, const float* __restrict__ be) {
    int c = threadIdx.x;
    if (c >= 32) return;
    double mean = dAcc[16 + c] / (double)N2;
    double var  = dAcc[48 + c] / (double)N2 - mean * mean;
    double sc = (double)g[c] / sqrt(var + 1e-5);
    dScale[c] = (float)sc;
    dShift[c] = (float)((double)be[c] - mean * sc);
}

// BN affine + LeakyReLU, in place; writes fp16 copy
__global__ void k_apply32(float* __restrict__ a, __half* __restrict__ ah) {
    int i = blockIdx.x * blockDim.x + threadIdx.x;
    int c = i & 31;
    float v = a[i] * dScale[c] + dShift[c];
    v = v > 0.f ? v : SLOPE * v;
    a[i]  = v;
    ah[i] = __float2half(v);
}

// layer2 final: T3 combine fused with 1-channel output + scalar BN stats
__global__ void k_mv_out2(const float* __restrict__ v, const __half* __restrict__ vh,
                          const float* __restrict__ p, const float* __restrict__ x3,
                          const int* __restrict__ src, const float* __restrict__ ew,
                          const float* __restrict__ W2) {
    int t = blockIdx.x * blockDim.x + threadIdx.x;
    int node = t >> 5;
    int lane = t & 31;
    int base = node * 16;
    int   sl = src[base + (lane & 15)];
    float wl = ew[base + (lane & 15)];
    float acc = 0.f;
#pragma unroll
    for (int e = 0; e < 16; e++) {
        int   s  = __shfl_sync(0xffffffffu, sl, e);
        float wt = __shfl_sync(0xffffffffu, wl, e);
        acc += wt * __half2float(__ldg(&vh[s * 32 + lane]));
    }
    int o = node * 32 + lane;
    float vv = __ldg(&v[o]), pp = __ldg(&p[o]);
    float T3 = (5.f * vv - 2.f * pp - acc) * (1.f / 3.f);
    float val = __ldg(&x3[o]) * W2[lane] + pp * W2[32 + lane] +
                vv * W2[64 + lane] + T3 * W2[96 + lane];
#pragma unroll
    for (int off = 16; off > 0; off >>= 1)
        val += __shfl_down_sync(0xffffffffu, val, off);
    __shared__ float sh_s[8], sh_q[8];
    int w = threadIdx.x >> 5;
    if (lane == 0) {                 // b2 dropped: BN-invariant
        dXfPre[node] = val;
        sh_s[w] = val;
        sh_q[w] = val * val;
    }
    __syncthreads();
    if (threadIdx.x == 0) {
        float s = 0, q = 0;
        for (int i = 0; i < 8; i++) { s += sh_s[i]; q += sh_q[i]; }
        atomicAdd(&dAcc[96], (double)s);
        atomicAdd(&dAcc[97], (double)q);
    }
}

// single block: layer-2 scalar BN prep -> dScale[32]/dShift[32]
__global__ void k_prep1(const float* __restrict__ g, const float* __restrict__ be) {
    double mean = dAcc[96] / (double)N2;
    double var  = dAcc[97] / (double)N2 - mean * mean;
    double sc = (double)g[0] / sqrt(var + 1e-5);
    dScale[32] = (float)sc;
    dShift[32] = (float)((double)be[0] - mean * sc);
}

__global__ void k_apply1() {
    int i = blockIdx.x * blockDim.x + threadIdx.x;
    if (i >= N2) return;
    float v = dXfPre[i] * dScale[32] + dShift[32];
    dXf[i] = v > 0.f ? v : SLOPE * v;
}

// ---------------- MLP head ----------------
// k-split GEMM: grid (36 k-slices, 4 row-groups), block 256 = output channel
__global__ void k_lin1(const float* __restrict__ W) {
    __shared__ float sm[16 * 128];
    int c = threadIdx.x;
    int jbase = blockIdx.x * 128;
    int rbase = blockIdx.y * 16;
    for (int i = c; i < 16 * 128; i += 256) {
        int r = i >> 7, j = i & 127, gj = jbase + j;
        sm[i] = (gj < E2c) ? dXf[(rbase + r) * E2c + gj] : 0.f;
    }
    __syncthreads();
    int jlim = E2c - jbase; if (jlim > 128) jlim = 128;
    float acc[16];
#pragma unroll
    for (int r = 0; r < 16; r++) acc[r] = 0.f;
    for (int j = 0; j < jlim; j++) {
        float w = __ldg(&W[(jbase + j) * 256 + c]);
#pragma unroll
        for (int r = 0; r < 16; r++) acc[r] += sm[r * 128 + j] * w;
    }
#pragma unroll
    for (int r = 0; r < 16; r++)
        atomicAdd(&dH1[(rbase + r) * 256 + c], acc[r]);
}

__global__ void k_bnrelu(float* __restrict__ H, const float* __restrict__ g,
                         const float* __restrict__ be, int C) {
    int c = threadIdx.x;
    if (c >= C) return;
    float s = 0, q = 0;
    for (int r = 0; r < Bq; r++) { float v = H[r * C + c]; s += v; q += v * v; }
    float mean = s / (float)Bq, var = q / (float)Bq - mean * mean;
    float sc = g[c] * rsqrtf(var + 1e-5f);
    float sh = be[c] - mean * sc;
    for (int r = 0; r < Bq; r++) {
        float v = H[r * C + c] * sc + sh;
        H[r * C + c] = fmaxf(v, 0.f);
    }
}

__global__ void k_lin2(const float* __restrict__ H1, const float* __restrict__ W,
                       const float* __restrict__ bias, float* __restrict__ H2) {
    __shared__ float row[256];
    int b = blockIdx.x, t = threadIdx.x;
    row[t] = H1[b * 256 + t];
    __syncthreads();
    if (t < 128) {
        float acc = bias[t];
        for (int j = 0; j < 256; j++)
            acc += row[j] * W[j * 128 + t];
        H2[b * 128 + t] = acc;
    }
}

__global__ void k_lin3(const float* __restrict__ H2, const float* __restrict__ W,
                       const float* __restrict__ bias, float* __restrict__ out) {
    int b = blockIdx.x, t = threadIdx.x;
    float p = H2[b * 128 + t] * W[t];
#pragma unroll
    for (int o = 16; o > 0; o >>= 1)
        p += __shfl_down_sync(0xffffffffu, p, o);
    __shared__ float sh[4];
    if ((t & 31) == 0) sh[t >> 5] = p;
    __syncthreads();
    if (t == 0) out[b] = sh[0] + sh[1] + sh[2] + sh[3] + bias[0];
}

// ---------------- launch ----------------
extern "C" void kernel_launch(void* const* d_in, const int* in_sizes, int n_in,
                              void* d_out, int out_size) {
    const float* x_s  = (const float*)d_in[0];
    const int*   ei1  = (const int*)d_in[1];
    const float* ew1  = (const float*)d_in[2];
    const int*   ei2  = (const int*)d_in[3];
    const float* ew2  = (const float*)d_in[4];
    const float* W0   = (const float*)d_in[5];
    const float* g0   = (const float*)d_in[7];
    const float* be0  = (const float*)d_in[8];
    const float* W1   = (const float*)d_in[9];
    const float* g1   = (const float*)d_in[11];
    const float* be1  = (const float*)d_in[12];
    const float* W2   = (const float*)d_in[13];
    const float* g2   = (const float*)d_in[15];
    const float* be2  = (const float*)d_in[16];
    const float* l1W  = (const float*)d_in[17];
    const float* l1b  = (const float*)d_in[18];
    const float* bn1g = (const float*)d_in[19];
    const float* bn1b = (const float*)d_in[20];
    const float* l2W  = (const float*)d_in[21];
    const float* l2b  = (const float*)d_in[22];
    const float* bn2g = (const float*)d_in[23];
    const float* bn2b = (const float*)d_in[24];
    const float* l3W  = (const float*)d_in[25];
    const float* l3b  = (const float*)d_in[26];

    const int* src1 = ei1;
    const int* src2 = ei2;

    float *pT1a, *pT2a, *pT3a, *pX2, *pT1, *pT2, *pOut, *pH1, *pH2;
    __half *pX2h, *pT1h, *pT2h, *pT3h, *pX3h;
    cudaGetSymbolAddress((void**)&pT1a, dT1a);
    cudaGetSymbolAddress((void**)&pT2a, dT2a);
    cudaGetSymbolAddress((void**)&pT3a, dT3a);
    cudaGetSymbolAddress((void**)&pX2, dX2);
    cudaGetSymbolAddress((void**)&pT1, dT1v);
    cudaGetSymbolAddress((void**)&pT2, dT2v);
    cudaGetSymbolAddress((void**)&pOut, dOutB);
    cudaGetSymbolAddress((void**)&pH1, dH1);
    cudaGetSymbolAddress((void**)&pH2, dH2);
    cudaGetSymbolAddress((void**)&pX2h, dX2h);
    cudaGetSymbolAddress((void**)&pT1h, dT1h);
    cudaGetSymbolAddress((void**)&pT2h, dT2h);
    cudaGetSymbolAddress((void**)&pT3h, dT3h);
    cudaGetSymbolAddress((void**)&pX3h, dX3h);

    const int NBV = (N2 * 32) / 256;   // 35912

    // ---- layer 0 (scalar Laguerre conv); launch 1 carries init tail ----
    k_mv_scalar<<<NE1 / 256 + 65, 256>>>(x_s, x_s, pT1a, src1, ew1, N1, 1.f, 0.f, 1.f, l1b);
    k_mv_scalar<<<NE1 / 256, 256>>>(pT1a, x_s, pT2a, src1, ew1, N1, 3.f, -1.f, 0.5f, l1b);
    k_mv_scalar<<<NE1 / 256, 256>>>(pT2a, pT1a, pT3a, src1, ew1, N1, 5.f, -2.f, 1.f / 3.f, l1b);
    k_stats0<<<562, 256>>>(x_s);
    k_prep0<<<1, 32>>>(W0, g0, be0);
    k_pool<<<NBV, 256>>>(x_s, W0);

    // ---- layer 1 (32ch Laguerre conv) ----
    k_mv_vec<<<NBV, 256>>>(pX2, pX2h, pX2, pT1, pT1h, src2, ew2, 1.f, 0.f, 1.f, 1);
    k_mv_vec<<<NBV, 256>>>(pT1, pT1h, pX2, pT2, pT2h, src2, ew2, 3.f, -1.f, 0.5f, 1);
    k_mv_vec<<<NBV, 256>>>(pT2, pT2h, pT1, pT2, pT3h, src2, ew2, 5.f, -2.f, 1.f / 3.f, 0);
    k_outgemm_mma<<<(N2 + 127) / 128, 256>>>(pX2h, pT1h, pT2h, pT3h, W1, pOut);
    k_stats32<<<1122, 256>>>(pOut);
    k_prep32<<<1, 32>>>(g1, be1);
    k_apply32<<<NBV, 256>>>(pOut, pX3h);               // in-place -> x3 (+fp16)

    // ---- layer 2 (32ch -> 1ch Laguerre conv, output fused) ----
    k_mv_vec<<<NBV, 256>>>(pOut, pX3h, pOut, pT1, pT1h, src2, ew2, 1.f, 0.f, 1.f, 1);
    k_mv_vec<<<NBV, 256>>>(pT1, pT1h, pOut, pT2, pT2h, src2, ew2, 3.f, -1.f, 0.5f, 1);
    k_mv_out2<<<NBV, 256>>>(pT2, pT2h, pT1, pOut, src2, ew2, W2);
    k_prep1<<<1, 1>>>(g2, be2);
    k_apply1<<<(N2 + 255) / 256, 256>>>();

    // ---- MLP head ----
    k_lin1<<<dim3(36, 4), 256>>>(l1W);
    k_bnrelu<<<1, 256>>>(pH1, bn1g, bn1b, 256);
    k_lin2<<<Bq, 256>>>(pH1, l2W, l2b, pH2);
    k_bnrelu<<<1, 128>>>(pH2, bn2g, bn2b, 128);
    k_lin3<<<Bq, 128>>>(pH2, l3W, l3b, (float*)d_out);
}